// round 9
// baseline (speedup 1.0000x reference)
#include <cuda_runtime.h>
#include <cuda_fp16.h>
#include <math.h>
#include <stdint.h>

#define NB 8
#define LQ 1024
#define HH 16
#define DD 64
#define EE 1024
#define ROWS (NB*HH*LQ)   // 131072 head-rows

// Scratch (static device globals — no allocation)
__device__ __half g_q[ROWS*DD];
__device__ __half g_k[ROWS*DD];
__device__ __half g_v[ROWS*DD];   // v' = x @ (Wv@Wfc), stored TRANSPOSED: [n,h,d,l]
__device__ float  g_Wvf[DD*DD];

__device__ __forceinline__ void mma_f16(float d[4],
        uint32_t a0, uint32_t a1, uint32_t a2, uint32_t a3,
        uint32_t b0, uint32_t b1) {
    asm volatile(
        "mma.sync.aligned.m16n8k16.row.col.f32.f16.f16.f32 "
        "{%0,%1,%2,%3},{%4,%5,%6,%7},{%8,%9},{%0,%1,%2,%3};"
        : "+f"(d[0]), "+f"(d[1]), "+f"(d[2]), "+f"(d[3])
        : "r"(a0), "r"(a1), "r"(a2), "r"(a3), "r"(b0), "r"(b1));
}

__device__ __forceinline__ void mma_f16_k8(float d[4],
        uint32_t a0, uint32_t a1, uint32_t b0) {
    asm volatile(
        "mma.sync.aligned.m16n8k8.row.col.f32.f16.f16.f32 "
        "{%0,%1,%2,%3},{%4,%5},{%6},{%0,%1,%2,%3};"
        : "+f"(d[0]), "+f"(d[1]), "+f"(d[2]), "+f"(d[3])
        : "r"(a0), "r"(a1), "r"(b0));
}

// streaming (evict-first) stores for write-once outputs
__device__ __forceinline__ void stcs_f2(float* p, float a, float b) {
    asm volatile("st.global.cs.v2.f32 [%0], {%1,%2};" :: "l"(p), "f"(a), "f"(b));
}
__device__ __forceinline__ void stcs_f4(float* p, float4 v) {
    asm volatile("st.global.cs.v4.f32 [%0], {%1,%2,%3,%4};"
                 :: "l"(p), "f"(v.x), "f"(v.y), "f"(v.z), "f"(v.w));
}

#define CP_ASYNC16(dst_u32, src_ptr) \
    asm volatile("cp.async.cg.shared.global [%0], [%1], 16;" :: "r"(dst_u32), "l"(src_ptr))
#define CP_COMMIT() asm volatile("cp.async.commit_group;" ::: "memory")
#define CP_WAIT(N)  asm volatile("cp.async.wait_group %0;" :: "n"(N) : "memory")

// ---------------------------------------------------------------------------
// prep: Wvf = Wv @ Wfc  (64x64 @ 64x64)
// ---------------------------------------------------------------------------
__global__ __launch_bounds__(1024) void prep_kernel(const float* __restrict__ Wv,
                                                    const float* __restrict__ Wfc) {
    __shared__ float wv[64*64];
    __shared__ float wf[64*64];
    int tid = threadIdx.x;
    for (int i = tid; i < 4096; i += 1024) { wv[i] = Wv[i]; wf[i] = Wfc[i]; }
    __syncthreads();
    int r = tid >> 4, c4 = (tid & 15) << 2;
    float4 acc = {0.f, 0.f, 0.f, 0.f};
    #pragma unroll 8
    for (int u = 0; u < 64; u++) {
        float a = wv[r*64 + u];
        float4 b = *(const float4*)&wf[u*64 + c4];
        acc.x += a*b.x; acc.y += a*b.y; acc.z += a*b.z; acc.w += a*b.w;
    }
    *(float4*)&g_Wvf[r*64 + c4] = acc;
}

// ---------------------------------------------------------------------------
// projection: per (n, h, 64-row l-tile): q = x@(Wq*0.06/32), k = x@Wk, v' = x@Wvf
// outputs fp16; g_v written transposed ([d][l])
// ---------------------------------------------------------------------------
__global__ __launch_bounds__(256) void proj_kernel(const float* __restrict__ x,
                                                   const float* __restrict__ Wq,
                                                   const float* __restrict__ Wk) {
    extern __shared__ float sm[];
    float* xs = sm;               // 64*65
    float* ws = xs + 64*65;       // 3 * 64*65
    float* os = ws + 3*64*65;     // 64*64
    const int tid = threadIdx.x;
    const int bid = blockIdx.x;
    const int n = bid >> 8, h = (bid >> 4) & 15, lt = bid & 15;
    const int l0 = lt << 6;
    const float qs = 0.06f / 32.0f;

    for (int idx = tid; idx < 1024; idx += 256) {
        int l = idx >> 4, t4 = (idx & 15) << 2;
        float4 v = *(const float4*)&x[(n*LQ + l0 + l)*EE + (h << 6) + t4];
        float* p = &xs[l*65 + t4];
        p[0] = v.x; p[1] = v.y; p[2] = v.z; p[3] = v.w;
    }
    for (int idx = tid; idx < 4096; idx += 256) {
        int t = idx >> 6, d = idx & 63;
        ws[t*65 + d]            = Wq[idx] * qs;
        ws[64*65 + t*65 + d]    = Wk[idx];
        ws[2*64*65 + t*65 + d]  = g_Wvf[idx];
    }
    __syncthreads();

    const int tl = tid & 15, td = tid >> 4;
    for (int w = 0; w < 3; w++) {
        const float* W = ws + w*64*65;
        float acc[4][4] = {};
        for (int t = 0; t < 64; t++) {
            float xv[4], wv[4];
            #pragma unroll
            for (int a = 0; a < 4; a++) xv[a] = xs[(tl*4 + a)*65 + t];
            #pragma unroll
            for (int b = 0; b < 4; b++) wv[b] = W[t*65 + td*4 + b];
            #pragma unroll
            for (int a = 0; a < 4; a++)
                #pragma unroll
                for (int b = 0; b < 4; b++) acc[a][b] += xv[a] * wv[b];
        }
        if (w < 2) {
            #pragma unroll
            for (int a = 0; a < 4; a++)
                #pragma unroll
                for (int b = 0; b < 4; b++)
                    os[(tl*4 + a)*64 + td*4 + b] = acc[a][b];
        } else {
            #pragma unroll
            for (int a = 0; a < 4; a++)
                #pragma unroll
                for (int b = 0; b < 4; b++)
                    os[(td*4 + b)*64 + tl*4 + a] = acc[a][b];
        }
        __syncthreads();
        if (w < 2) {
            __half* gp = (w == 0 ? g_q : g_k) + ((n*HH + h)*LQ + l0)*DD;
            for (int idx = tid; idx < 2048; idx += 256) {
                int row = idx >> 5, d2 = (idx & 31) << 1;
                __half2 hv = __floats2half2_rn(os[row*64 + d2], os[row*64 + d2 + 1]);
                *(__half2*)(gp + row*64 + d2) = hv;
            }
        } else {
            __half* gp = g_v + ((n*HH + h)*DD)*LQ + l0;
            for (int idx = tid; idx < 2048; idx += 256) {
                int d = idx >> 5, l2 = (idx & 31) << 1;
                __half2 hv = __floats2half2_rn(os[d*64 + l2], os[d*64 + l2 + 1]);
                *(__half2*)(gp + d*LQ + l2) = hv;
            }
        }
        __syncthreads();
    }
}

// ---------------------------------------------------------------------------
// attention v5 (streaming, scores never in smem): 32-query block, 512 thr, 16 warps.
//  phase1: warp owns 8 key-cols/chunk for all 32 rows. After each chunk's mma,
//          e=exp(s) immediately (scores tiny, |s|<0.1: no max needed),
//          row-sums accumulated online, e packed fp16 into pe[8][2][2] regs.
//  sum reduce: quad shfl + 32x16 smem (one sync round; no max round).
//  normalize: p = e*inv in fp32 -> attn written straight from regs (st.cs);
//          repacked fp16 in-register as m16n8k8 A-fragments (no Ph!).
//  phase3: warp's phase-1 cols == its k-keys. B from V^T chunk smem,
//          oacc[2][8][4] partial over warp's 64 keys; 2-batch smem tree reduce.
// smem: KB 2x16K | VB 2x16K | Qs 4K | redS 2K = 71680 B
//       reduce overlay [0, 69632) = 8 slots * 32 rows * 68 floats
// ---------------------------------------------------------------------------
#define SMEM_KB   0
#define SMEM_VB   32768
#define SMEM_QS   65536
#define SMEM_REDS 69632
#define SMEM_TOT  71680

__global__ __launch_bounds__(512, 1) void attn_kernel(float* __restrict__ attn,
                                                      float* __restrict__ out) {
    extern __shared__ char smraw[];
    __half* Qs   = (__half*)(smraw + SMEM_QS);
    float*  redS = (float*)(smraw + SMEM_REDS);
    float*  red  = (float*)(smraw);               // overlay after V dead
    const uint32_t sbase = (uint32_t)__cvta_generic_to_shared(smraw);

    const int tid = threadIdx.x, w = tid >> 5, lane = tid & 31;
    const int bid = blockIdx.x;
    const int n = bid >> 9, h = (bid >> 5) & 15, qb = bid & 31;
    const int q0 = qb << 5;
    const int base = (n*HH + h)*LQ;
    const int g = lane >> 2, tg = lane & 3;

    const __half* kg0 = g_k + (size_t)base * DD;
    const __half* vg0 = g_v + (size_t)(n*HH + h) * DD * LQ;

    // issue K chunk 0
    #pragma unroll
    for (int t = tid; t < 1024; t += 512) {
        int r = t >> 3, c8 = t & 7;
        CP_ASYNC16(sbase + SMEM_KB + (r*64 + ((c8 ^ (r & 7)) << 3))*2,
                   kg0 + r*64 + c8*8);
    }
    CP_COMMIT();

    // load Q tile (32x64 half), swizzled
    if (tid < 256) {
        int r = tid >> 3, c8 = tid & 7;
        const uint4* src = (const uint4*)(g_q + (size_t)(base + q0 + r)*DD) + c8;
        *(uint4*)(Qs + r*64 + ((c8 ^ (r & 7)) << 3)) = *src;
    }
    __syncthreads();

    // Q fragments: 2 row-tiles x 4 k-steps
    uint32_t qf[2][4][4];
    #pragma unroll
    for (int rt = 0; rt < 2; rt++) {
        int r0 = rt*16 + g, r1 = r0 + 8;
        #pragma unroll
        for (int kk = 0; kk < 4; kk++) {
            int c8a = 2*kk, c8b = 2*kk + 1;
            qf[rt][kk][0] = *(const uint32_t*)(Qs + r0*64 + ((c8a ^ g) << 3) + 2*tg);
            qf[rt][kk][1] = *(const uint32_t*)(Qs + r1*64 + ((c8a ^ g) << 3) + 2*tg);
            qf[rt][kk][2] = *(const uint32_t*)(Qs + r0*64 + ((c8b ^ g) << 3) + 2*tg);
            qf[rt][kk][3] = *(const uint32_t*)(Qs + r1*64 + ((c8b ^ g) << 3) + 2*tg);
        }
    }

    // ---- phase 1: QK^T chunk-streamed; e=exp(s) to fp16 regs + online sums ----
    uint32_t pe[8][2][2];          // [chunk][rt][z]: half2 pairs
    float sums[2][2] = {{0.f, 0.f}, {0.f, 0.f}};
    const int krow = w*8 + g;      // key row (n index) this warp owns

    #pragma unroll
    for (int c = 0; c < 8; c++) {
        CP_WAIT(0);
        __syncthreads();
        if (c < 7) {          // prefetch next K chunk
            const __half* kc = kg0 + (size_t)(c + 1)*128*DD;
            #pragma unroll
            for (int t = tid; t < 1024; t += 512) {
                int r = t >> 3, c8 = t & 7;
                CP_ASYNC16(sbase + SMEM_KB + ((c + 1) & 1)*16384
                           + (r*64 + ((c8 ^ (r & 7)) << 3))*2,
                           kc + r*64 + c8*8);
            }
            CP_COMMIT();
        } else {              // prefetch V chunk 0
            #pragma unroll
            for (int t = tid; t < 1024; t += 512) {
                int r = t >> 4, c8 = t & 15;
                CP_ASYNC16(sbase + SMEM_VB + (r*128 + ((c8 ^ (r & 7)) << 3))*2,
                           vg0 + r*LQ + c8*8);
            }
            CP_COMMIT();
        }
        const __half* Kc = (const __half*)(smraw + SMEM_KB + (c & 1)*16384);
        float a[2][4] = {{0.f,0.f,0.f,0.f},{0.f,0.f,0.f,0.f}};
        #pragma unroll
        for (int kk = 0; kk < 4; kk++) {
            uint32_t b0 = *(const uint32_t*)(Kc + krow*64 + (((2*kk)   ^ g) << 3) + 2*tg);
            uint32_t b1 = *(const uint32_t*)(Kc + krow*64 + (((2*kk+1) ^ g) << 3) + 2*tg);
            #pragma unroll
            for (int rt = 0; rt < 2; rt++)
                mma_f16(a[rt], qf[rt][kk][0], qf[rt][kk][1],
                        qf[rt][kk][2], qf[rt][kk][3], b0, b1);
        }
        #pragma unroll
        for (int rt = 0; rt < 2; rt++) {
            float e0 = __expf(a[rt][0]);
            float e1 = __expf(a[rt][1]);
            float e2 = __expf(a[rt][2]);
            float e3 = __expf(a[rt][3]);
            sums[rt][0] += e0 + e1;
            sums[rt][1] += e2 + e3;
            __half2 h0 = __floats2half2_rn(e0, e1);
            __half2 h1 = __floats2half2_rn(e2, e3);
            pe[c][rt][0] = *(uint32_t*)&h0;
            pe[c][rt][1] = *(uint32_t*)&h1;
        }
    }
    // issue V chunk 1
    #pragma unroll
    for (int t = tid; t < 1024; t += 512) {
        int r = t >> 4, c8 = t & 15;
        CP_ASYNC16(sbase + SMEM_VB + 16384 + (r*128 + ((c8 ^ (r & 7)) << 3))*2,
                   vg0 + r*LQ + 128 + c8*8);
    }
    CP_COMMIT();

    // ---- sum reduce (no max needed: |s| < 0.1) ----
    #pragma unroll
    for (int rt = 0; rt < 2; rt++)
        #pragma unroll
        for (int z = 0; z < 2; z++) {
            float s = sums[rt][z];
            s += __shfl_xor_sync(0xffffffffu, s, 1);
            s += __shfl_xor_sync(0xffffffffu, s, 2);
            sums[rt][z] = s;
        }
    if (tg == 0) {
        #pragma unroll
        for (int rt = 0; rt < 2; rt++)
            #pragma unroll
            for (int z = 0; z < 2; z++)
                redS[(rt*16 + z*8 + g)*16 + w] = sums[rt][z];
    }
    __syncthreads();
    float inv[2][2];
    #pragma unroll
    for (int rt = 0; rt < 2; rt++)
        #pragma unroll
        for (int z = 0; z < 2; z++) {
            int row = rt*16 + z*8 + g;
            float s = 0.f;
            #pragma unroll
            for (int k = 0; k < 16; k++) s += redS[row*16 + k];
            inv[rt][z] = 1.0f / s;
        }

    // ---- normalize: attn written from regs (st.cs); pe repacked as A-frags ----
    #pragma unroll
    for (int c = 0; c < 8; c++)
        #pragma unroll
        for (int rt = 0; rt < 2; rt++)
            #pragma unroll
            for (int z = 0; z < 2; z++) {
                int row = rt*16 + z*8 + g;
                float2 e = __half22float2(*(__half2*)&pe[c][rt][z]);
                float p0 = e.x * inv[rt][z];
                float p1 = e.y * inv[rt][z];
                stcs_f2(attn + (size_t)(base + q0 + row)*1024
                        + c*128 + w*8 + 2*tg, p0, p1);
                __half2 hp = __floats2half2_rn(p0, p1);
                pe[c][rt][z] = *(uint32_t*)&hp;
            }

    // ---- phase 3: out partial over this warp's 64 keys (m16n8k8, A in regs) ----
    float oacc[2][8][4];
    #pragma unroll
    for (int rt = 0; rt < 2; rt++)
        #pragma unroll
        for (int nt = 0; nt < 8; nt++)
            #pragma unroll
            for (int j = 0; j < 4; j++) oacc[rt][nt][j] = 0.f;

    #pragma unroll
    for (int c = 0; c < 8; c++) {
        CP_WAIT(1);
        if (c == 7) { CP_WAIT(0); }
        __syncthreads();
        const __half* Vc = (const __half*)(smraw + SMEM_VB + (c & 1)*16384);
        #pragma unroll
        for (int nt = 0; nt < 8; nt++) {
            int vrow = nt*8 + g;   // dim index (vrow & 7 == g)
            uint32_t b = *(const uint32_t*)(Vc + vrow*128 + ((w ^ g) << 3) + 2*tg);
            mma_f16_k8(oacc[0][nt], pe[c][0][0], pe[c][0][1], b);
            mma_f16_k8(oacc[1][nt], pe[c][1][0], pe[c][1][1], b);
        }
        __syncthreads();
        if (c + 2 < 8) {   // prefetch V chunk c+2 into buffer (c&1)
            const __half* vc = vg0 + (size_t)(c + 2)*128;
            #pragma unroll
            for (int t = tid; t < 1024; t += 512) {
                int r = t >> 4, c8 = t & 15;
                CP_ASYNC16(sbase + SMEM_VB + (c & 1)*16384
                           + (r*128 + ((c8 ^ (r & 7)) << 3))*2,
                           vc + r*LQ + c8*8);
            }
            CP_COMMIT();
        }
    }

    // ---- 2-batch 8-slot tree reduce over 16 warps (overlay on K/V/Qs) ----
    const int orow = tid >> 4, od4 = (tid & 15) << 2;
    float4 osum = make_float4(0.f, 0.f, 0.f, 0.f);
    #pragma unroll
    for (int batch = 0; batch < 2; batch++) {
        if ((w >> 3) == batch) {
            int slot = w & 7;
            #pragma unroll
            for (int rt = 0; rt < 2; rt++)
                #pragma unroll
                for (int nt = 0; nt < 8; nt++) {
                    int d0 = nt*8 + 2*tg;
                    int r0 = rt*16 + g, r1 = r0 + 8;
                    *(float2*)&red[slot*2176 + r0*68 + d0]
                        = make_float2(oacc[rt][nt][0], oacc[rt][nt][1]);
                    *(float2*)&red[slot*2176 + r1*68 + d0]
                        = make_float2(oacc[rt][nt][2], oacc[rt][nt][3]);
                }
        }
        __syncthreads();
        #pragma unroll
        for (int s = 0; s < 8; s++) {
            float4 v = *(const float4*)&red[s*2176 + orow*68 + od4];
            osum.x += v.x; osum.y += v.y; osum.z += v.z; osum.w += v.w;
        }
        __syncthreads();
    }
    stcs_f4(&out[((size_t)(n*LQ + q0 + orow)*HH + h)*DD + od4], osum);
}

// ---------------------------------------------------------------------------
extern "C" void kernel_launch(void* const* d_in, const int* in_sizes, int n_in,
                              void* d_out, int out_size) {
    const float* x   = (const float*)d_in[0];
    const float* Wq  = (const float*)d_in[1];
    const float* Wk  = (const float*)d_in[2];
    const float* Wv  = (const float*)d_in[3];
    const float* Wfc = (const float*)d_in[4];

    float* out  = (float*)d_out;
    float* attn = out + (size_t)NB * LQ * EE;   // out first, then attn

    prep_kernel<<<1, 1024>>>(Wv, Wfc);

    size_t proj_smem = (size_t)(4*64*65 + 64*64) * sizeof(float);   // 82944
    cudaFuncSetAttribute(proj_kernel,
                         cudaFuncAttributeMaxDynamicSharedMemorySize,
                         (int)proj_smem);
    proj_kernel<<<NB*HH*16, 256, proj_smem>>>(x, Wq, Wk);

    cudaFuncSetAttribute(attn_kernel,
                         cudaFuncAttributeMaxDynamicSharedMemorySize,
                         SMEM_TOT);
    attn_kernel<<<NB*HH*32, 512, SMEM_TOT>>>(attn, out);
}

// round 10
// speedup vs baseline: 1.2321x; 1.2321x over previous
#include <cuda_runtime.h>
#include <cuda_fp16.h>
#include <math.h>
#include <stdint.h>

#define NB 8
#define LQ 1024
#define HH 16
#define DD 64
#define EE 1024
#define ROWS (NB*HH*LQ)   // 131072 head-rows

// Scratch (static device globals — no allocation)
__device__ __half g_q[ROWS*DD];
__device__ __half g_k[ROWS*DD];
__device__ __half g_v[ROWS*DD];   // v' = x @ (Wv@Wfc), stored TRANSPOSED: [n,h,d,l]
__device__ float  g_Wvf[DD*DD];

__device__ __forceinline__ void mma_f16(float d[4],
        uint32_t a0, uint32_t a1, uint32_t a2, uint32_t a3,
        uint32_t b0, uint32_t b1) {
    asm volatile(
        "mma.sync.aligned.m16n8k16.row.col.f32.f16.f16.f32 "
        "{%0,%1,%2,%3},{%4,%5,%6,%7},{%8,%9},{%0,%1,%2,%3};"
        : "+f"(d[0]), "+f"(d[1]), "+f"(d[2]), "+f"(d[3])
        : "r"(a0), "r"(a1), "r"(a2), "r"(a3), "r"(b0), "r"(b1));
}

__device__ __forceinline__ void mma_f16_k8(float d[4],
        uint32_t a0, uint32_t a1, uint32_t b0) {
    asm volatile(
        "mma.sync.aligned.m16n8k8.row.col.f32.f16.f16.f32 "
        "{%0,%1,%2,%3},{%4,%5},{%6},{%0,%1,%2,%3};"
        : "+f"(d[0]), "+f"(d[1]), "+f"(d[2]), "+f"(d[3])
        : "r"(a0), "r"(a1), "r"(b0));
}

// streaming (evict-first) stores for write-once outputs
__device__ __forceinline__ void stcs_f2(float* p, float a, float b) {
    asm volatile("st.global.cs.v2.f32 [%0], {%1,%2};" :: "l"(p), "f"(a), "f"(b));
}
__device__ __forceinline__ void stcs_f4(float* p, float4 v) {
    asm volatile("st.global.cs.v4.f32 [%0], {%1,%2,%3,%4};"
                 :: "l"(p), "f"(v.x), "f"(v.y), "f"(v.z), "f"(v.w));
}

#define CP_ASYNC16(dst_u32, src_ptr) \
    asm volatile("cp.async.cg.shared.global [%0], [%1], 16;" :: "r"(dst_u32), "l"(src_ptr))
#define CP_COMMIT() asm volatile("cp.async.commit_group;" ::: "memory")
#define CP_WAIT(N)  asm volatile("cp.async.wait_group %0;" :: "n"(N) : "memory")

// ---------------------------------------------------------------------------
// prep: Wvf = Wv @ Wfc  (64x64 @ 64x64)
// ---------------------------------------------------------------------------
__global__ __launch_bounds__(1024) void prep_kernel(const float* __restrict__ Wv,
                                                    const float* __restrict__ Wfc) {
    __shared__ float wv[64*64];
    __shared__ float wf[64*64];
    int tid = threadIdx.x;
    for (int i = tid; i < 4096; i += 1024) { wv[i] = Wv[i]; wf[i] = Wfc[i]; }
    __syncthreads();
    int r = tid >> 4, c4 = (tid & 15) << 2;
    float4 acc = {0.f, 0.f, 0.f, 0.f};
    #pragma unroll 8
    for (int u = 0; u < 64; u++) {
        float a = wv[r*64 + u];
        float4 b = *(const float4*)&wf[u*64 + c4];
        acc.x += a*b.x; acc.y += a*b.y; acc.z += a*b.z; acc.w += a*b.w;
    }
    *(float4*)&g_Wvf[r*64 + c4] = acc;
}

// ---------------------------------------------------------------------------
// projection: per (n, h, 64-row l-tile): q = x@(Wq*0.06/32), k = x@Wk, v' = x@Wvf
// outputs fp16; g_v written transposed ([d][l])
// ---------------------------------------------------------------------------
__global__ __launch_bounds__(256) void proj_kernel(const float* __restrict__ x,
                                                   const float* __restrict__ Wq,
                                                   const float* __restrict__ Wk) {
    extern __shared__ float sm[];
    float* xs = sm;               // 64*65
    float* ws = xs + 64*65;       // 3 * 64*65
    float* os = ws + 3*64*65;     // 64*64
    const int tid = threadIdx.x;
    const int bid = blockIdx.x;
    const int n = bid >> 8, h = (bid >> 4) & 15, lt = bid & 15;
    const int l0 = lt << 6;
    const float qs = 0.06f / 32.0f;

    for (int idx = tid; idx < 1024; idx += 256) {
        int l = idx >> 4, t4 = (idx & 15) << 2;
        float4 v = *(const float4*)&x[(n*LQ + l0 + l)*EE + (h << 6) + t4];
        float* p = &xs[l*65 + t4];
        p[0] = v.x; p[1] = v.y; p[2] = v.z; p[3] = v.w;
    }
    for (int idx = tid; idx < 4096; idx += 256) {
        int t = idx >> 6, d = idx & 63;
        ws[t*65 + d]            = Wq[idx] * qs;
        ws[64*65 + t*65 + d]    = Wk[idx];
        ws[2*64*65 + t*65 + d]  = g_Wvf[idx];
    }
    __syncthreads();

    const int tl = tid & 15, td = tid >> 4;
    for (int w = 0; w < 3; w++) {
        const float* W = ws + w*64*65;
        float acc[4][4] = {};
        for (int t = 0; t < 64; t++) {
            float xv[4], wv[4];
            #pragma unroll
            for (int a = 0; a < 4; a++) xv[a] = xs[(tl*4 + a)*65 + t];
            #pragma unroll
            for (int b = 0; b < 4; b++) wv[b] = W[t*65 + td*4 + b];
            #pragma unroll
            for (int a = 0; a < 4; a++)
                #pragma unroll
                for (int b = 0; b < 4; b++) acc[a][b] += xv[a] * wv[b];
        }
        if (w < 2) {
            #pragma unroll
            for (int a = 0; a < 4; a++)
                #pragma unroll
                for (int b = 0; b < 4; b++)
                    os[(tl*4 + a)*64 + td*4 + b] = acc[a][b];
        } else {
            #pragma unroll
            for (int a = 0; a < 4; a++)
                #pragma unroll
                for (int b = 0; b < 4; b++)
                    os[(td*4 + b)*64 + tl*4 + a] = acc[a][b];
        }
        __syncthreads();
        if (w < 2) {
            __half* gp = (w == 0 ? g_q : g_k) + ((n*HH + h)*LQ + l0)*DD;
            for (int idx = tid; idx < 2048; idx += 256) {
                int row = idx >> 5, d2 = (idx & 31) << 1;
                __half2 hv = __floats2half2_rn(os[row*64 + d2], os[row*64 + d2 + 1]);
                *(__half2*)(gp + row*64 + d2) = hv;
            }
        } else {
            __half* gp = g_v + ((n*HH + h)*DD)*LQ + l0;
            for (int idx = tid; idx < 2048; idx += 256) {
                int d = idx >> 5, l2 = (idx & 31) << 1;
                __half2 hv = __floats2half2_rn(os[d*64 + l2], os[d*64 + l2 + 1]);
                *(__half2*)(gp + d*LQ + l2) = hv;
            }
        }
        __syncthreads();
    }
}

// ---------------------------------------------------------------------------
// attention v6: 16-query block, 256 threads, 8 warps, 2 BLOCKS PER SM.
//  phase1: warp owns 16 key-cols/chunk (nt=0,1) for all 16 rows.
//          e = exp(s) kept in FP32 regs ef[8][2][4]; online row-sums.
//  sum reduce: quad shfl + 16x8 smem (single round, no max: |s|<0.1).
//  normalize: attn written from fp32 regs (st.cs); P packed fp16 in-register
//          as m16n8k8 A-frags pef[8][2][2] (phase-1 nt == phase-3 k-group).
//  phase3: warp partial over its 128 keys x 16 rows x 64 dims (oacc[8][4]),
//          single-pass 8-slot smem reduce (overlay on dead K/V buffers).
// smem: KB 2x16K | VB 2x16K | Qs 2K | redS 512B = 68096 B -> 2 blocks/SM
// ---------------------------------------------------------------------------
#define SMEM_KB   0
#define SMEM_VB   32768
#define SMEM_QS   65536
#define SMEM_REDS 67584
#define SMEM_TOT  68096

__global__ __launch_bounds__(256, 2) void attn_kernel(float* __restrict__ attn,
                                                      float* __restrict__ out) {
    extern __shared__ char smraw[];
    __half* Qs   = (__half*)(smraw + SMEM_QS);
    float*  redS = (float*)(smraw + SMEM_REDS);
    float*  red  = (float*)(smraw);               // overlay after K/V dead
    const uint32_t sbase = (uint32_t)__cvta_generic_to_shared(smraw);

    const int tid = threadIdx.x, w = tid >> 5, lane = tid & 31;
    const int bid = blockIdx.x;
    const int n = bid >> 10, h = (bid >> 6) & 15, qb = bid & 63;
    const int q0 = qb << 4;
    const int base = (n*HH + h)*LQ;
    const int g = lane >> 2, tg = lane & 3;

    const __half* kg0 = g_k + (size_t)base * DD;
    const __half* vg0 = g_v + (size_t)(n*HH + h) * DD * LQ;

    // issue K chunk 0 (1024 x 16B, 4 per thread)
    #pragma unroll
    for (int t = tid; t < 1024; t += 256) {
        int r = t >> 3, c8 = t & 7;
        CP_ASYNC16(sbase + SMEM_KB + (r*64 + ((c8 ^ (r & 7)) << 3))*2,
                   kg0 + r*64 + c8*8);
    }
    CP_COMMIT();

    // load Q tile (16x64 half), swizzled
    if (tid < 128) {
        int r = tid >> 3, c8 = tid & 7;
        const uint4* src = (const uint4*)(g_q + (size_t)(base + q0 + r)*DD) + c8;
        *(uint4*)(Qs + r*64 + ((c8 ^ (r & 7)) << 3)) = *src;
    }
    __syncthreads();

    // Q fragments: 4 k-steps
    uint32_t qf[4][4];
    {
        int r0 = g, r1 = g + 8;
        #pragma unroll
        for (int kk = 0; kk < 4; kk++) {
            int c8a = 2*kk, c8b = 2*kk + 1;
            qf[kk][0] = *(const uint32_t*)(Qs + r0*64 + ((c8a ^ g) << 3) + 2*tg);
            qf[kk][1] = *(const uint32_t*)(Qs + r1*64 + ((c8a ^ g) << 3) + 2*tg);
            qf[kk][2] = *(const uint32_t*)(Qs + r0*64 + ((c8b ^ g) << 3) + 2*tg);
            qf[kk][3] = *(const uint32_t*)(Qs + r1*64 + ((c8b ^ g) << 3) + 2*tg);
        }
    }

    // ---- phase 1: QK^T chunk-streamed; e = exp(s) in FP32 regs ----
    float ef[8][2][4];             // [chunk][nt][val]
    float sums[2] = {0.f, 0.f};    // rows g, g+8

    #pragma unroll
    for (int c = 0; c < 8; c++) {
        CP_WAIT(0);
        __syncthreads();
        if (c < 7) {          // prefetch next K chunk
            const __half* kc = kg0 + (size_t)(c + 1)*128*DD;
            #pragma unroll
            for (int t = tid; t < 1024; t += 256) {
                int r = t >> 3, c8 = t & 7;
                CP_ASYNC16(sbase + SMEM_KB + ((c + 1) & 1)*16384
                           + (r*64 + ((c8 ^ (r & 7)) << 3))*2,
                           kc + r*64 + c8*8);
            }
            CP_COMMIT();
        } else {              // prefetch V chunk 0 (64 rows x 128 cols)
            #pragma unroll
            for (int t = tid; t < 1024; t += 256) {
                int r = t >> 4, c8 = t & 15;
                CP_ASYNC16(sbase + SMEM_VB + (r*128 + ((c8 ^ (r & 7)) << 3))*2,
                           vg0 + r*LQ + c8*8);
            }
            CP_COMMIT();
        }
        const __half* Kc = (const __half*)(smraw + SMEM_KB + (c & 1)*16384);
        float a[2][4] = {{0.f,0.f,0.f,0.f},{0.f,0.f,0.f,0.f}};
        #pragma unroll
        for (int kk = 0; kk < 4; kk++) {
            #pragma unroll
            for (int nt = 0; nt < 2; nt++) {
                int krow = w*16 + nt*8 + g;
                uint32_t b0 = *(const uint32_t*)(Kc + krow*64 + (((2*kk)   ^ g) << 3) + 2*tg);
                uint32_t b1 = *(const uint32_t*)(Kc + krow*64 + (((2*kk+1) ^ g) << 3) + 2*tg);
                mma_f16(a[nt], qf[kk][0], qf[kk][1], qf[kk][2], qf[kk][3], b0, b1);
            }
        }
        #pragma unroll
        for (int nt = 0; nt < 2; nt++) {
            float e0 = __expf(a[nt][0]);
            float e1 = __expf(a[nt][1]);
            float e2 = __expf(a[nt][2]);
            float e3 = __expf(a[nt][3]);
            sums[0] += e0 + e1;
            sums[1] += e2 + e3;
            ef[c][nt][0] = e0; ef[c][nt][1] = e1;
            ef[c][nt][2] = e2; ef[c][nt][3] = e3;
        }
    }
    // issue V chunk 1
    #pragma unroll
    for (int t = tid; t < 256*4; t += 256) {
        int tt = t;
        int r = tt >> 4, c8 = tt & 15;
        CP_ASYNC16(sbase + SMEM_VB + 16384 + (r*128 + ((c8 ^ (r & 7)) << 3))*2,
                   vg0 + r*LQ + 128 + c8*8);
    }
    CP_COMMIT();

    // ---- sum reduce (no max needed: |s| < 0.1) ----
    #pragma unroll
    for (int z = 0; z < 2; z++) {
        float s = sums[z];
        s += __shfl_xor_sync(0xffffffffu, s, 1);
        s += __shfl_xor_sync(0xffffffffu, s, 2);
        sums[z] = s;
    }
    if (tg == 0) {
        redS[(g)*8 + w]     = sums[0];
        redS[(g+8)*8 + w]   = sums[1];
    }
    __syncthreads();
    float inv[2];
    #pragma unroll
    for (int z = 0; z < 2; z++) {
        int row = z*8 + g;
        float s = 0.f;
        #pragma unroll
        for (int k = 0; k < 8; k++) s += redS[row*8 + k];
        inv[z] = 1.0f / s;
    }

    // ---- normalize: attn from fp32 regs (st.cs); pack fp16 A-frags ----
    uint32_t pef[8][2][2];
    #pragma unroll
    for (int c = 0; c < 8; c++)
        #pragma unroll
        for (int nt = 0; nt < 2; nt++) {
            float p0 = ef[c][nt][0] * inv[0];
            float p1 = ef[c][nt][1] * inv[0];
            float p2 = ef[c][nt][2] * inv[1];
            float p3 = ef[c][nt][3] * inv[1];
            int colb = c*128 + w*16 + nt*8 + 2*tg;
            stcs_f2(attn + (size_t)(base + q0 + g)*1024 + colb,     p0, p1);
            stcs_f2(attn + (size_t)(base + q0 + g + 8)*1024 + colb, p2, p3);
            __half2 h0 = __floats2half2_rn(p0, p1);
            __half2 h1 = __floats2half2_rn(p2, p3);
            pef[c][nt][0] = *(uint32_t*)&h0;
            pef[c][nt][1] = *(uint32_t*)&h1;
        }

    // ---- phase 3: out partial over warp's 128 keys (m16n8k8, A in regs) ----
    float oacc[8][4];
    #pragma unroll
    for (int nt = 0; nt < 8; nt++)
        #pragma unroll
        for (int j = 0; j < 4; j++) oacc[nt][j] = 0.f;

    #pragma unroll
    for (int c = 0; c < 8; c++) {
        CP_WAIT(1);
        if (c == 7) { CP_WAIT(0); }
        __syncthreads();
        const __half* Vc = (const __half*)(smraw + SMEM_VB + (c & 1)*16384);
        #pragma unroll
        for (int kk = 0; kk < 2; kk++) {
            #pragma unroll
            for (int nt = 0; nt < 8; nt++) {
                int vrow = nt*8 + g;   // dim index (vrow & 7 == g)
                uint32_t b = *(const uint32_t*)(Vc + vrow*128
                              + (((w*2 + kk) ^ g) << 3) + 2*tg);
                mma_f16_k8(oacc[nt], pef[c][kk][0], pef[c][kk][1], b);
            }
        }
        __syncthreads();
        if (c + 2 < 8) {   // prefetch V chunk c+2 into buffer (c&1)
            const __half* vc = vg0 + (size_t)(c + 2)*128;
            #pragma unroll
            for (int t = tid; t < 1024; t += 256) {
                int r = t >> 4, c8 = t & 15;
                CP_ASYNC16(sbase + SMEM_VB + (c & 1)*16384
                           + (r*128 + ((c8 ^ (r & 7)) << 3))*2,
                           vc + r*LQ + c8*8);
            }
            CP_COMMIT();
        }
    }

    // ---- single-pass 8-slot reduce (overlay on dead K/V smem) ----
    {
        int slot = w;
        #pragma unroll
        for (int nt = 0; nt < 8; nt++) {
            int d0 = nt*8 + 2*tg;
            *(float2*)&red[slot*1088 + g*68 + d0]
                = make_float2(oacc[nt][0], oacc[nt][1]);
            *(float2*)&red[slot*1088 + (g+8)*68 + d0]
                = make_float2(oacc[nt][2], oacc[nt][3]);
        }
    }
    __syncthreads();
    {
        int row = tid >> 4, d4 = (tid & 15) << 2;
        float4 s = make_float4(0.f, 0.f, 0.f, 0.f);
        #pragma unroll
        for (int k = 0; k < 8; k++) {
            float4 v = *(const float4*)&red[k*1088 + row*68 + d4];
            s.x += v.x; s.y += v.y; s.z += v.z; s.w += v.w;
        }
        stcs_f4(&out[((size_t)(n*LQ + q0 + row)*HH + h)*DD + d4], s);
    }
}

// ---------------------------------------------------------------------------
extern "C" void kernel_launch(void* const* d_in, const int* in_sizes, int n_in,
                              void* d_out, int out_size) {
    const float* x   = (const float*)d_in[0];
    const float* Wq  = (const float*)d_in[1];
    const float* Wk  = (const float*)d_in[2];
    const float* Wv  = (const float*)d_in[3];
    const float* Wfc = (const float*)d_in[4];

    float* out  = (float*)d_out;
    float* attn = out + (size_t)NB * LQ * EE;   // out first, then attn

    prep_kernel<<<1, 1024>>>(Wv, Wfc);

    size_t proj_smem = (size_t)(4*64*65 + 64*64) * sizeof(float);   // 82944
    cudaFuncSetAttribute(proj_kernel,
                         cudaFuncAttributeMaxDynamicSharedMemorySize,
                         (int)proj_smem);
    proj_kernel<<<NB*HH*16, 256, proj_smem>>>(x, Wq, Wk);

    cudaFuncSetAttribute(attn_kernel,
                         cudaFuncAttributeMaxDynamicSharedMemorySize,
                         SMEM_TOT);
    attn_kernel<<<NB*HH*64, 256, SMEM_TOT>>>(attn, out);
}

// round 11
// speedup vs baseline: 1.4179x; 1.1508x over previous
#include <cuda_runtime.h>
#include <cuda_fp16.h>
#include <math.h>
#include <stdint.h>

#define NB 8
#define LQ 1024
#define HH 16
#define DD 64
#define EE 1024
#define ROWS (NB*HH*LQ)   // 131072 head-rows

// Scratch (static device globals — no allocation)
__device__ __half g_q[ROWS*DD];
__device__ __half g_k[ROWS*DD];
__device__ __half g_v[ROWS*DD];   // v' = x @ (Wv@Wfc), stored TRANSPOSED: [n,h,d,l]
__device__ float  g_Wvf[DD*DD];

__device__ __forceinline__ void mma_f16(float d[4],
        uint32_t a0, uint32_t a1, uint32_t a2, uint32_t a3,
        uint32_t b0, uint32_t b1) {
    asm volatile(
        "mma.sync.aligned.m16n8k16.row.col.f32.f16.f16.f32 "
        "{%0,%1,%2,%3},{%4,%5,%6,%7},{%8,%9},{%0,%1,%2,%3};"
        : "+f"(d[0]), "+f"(d[1]), "+f"(d[2]), "+f"(d[3])
        : "r"(a0), "r"(a1), "r"(a2), "r"(a3), "r"(b0), "r"(b1));
}

__device__ __forceinline__ void mma_f16_k8(float d[4],
        uint32_t a0, uint32_t a1, uint32_t b0) {
    asm volatile(
        "mma.sync.aligned.m16n8k8.row.col.f32.f16.f16.f32 "
        "{%0,%1,%2,%3},{%4,%5},{%6},{%0,%1,%2,%3};"
        : "+f"(d[0]), "+f"(d[1]), "+f"(d[2]), "+f"(d[3])
        : "r"(a0), "r"(a1), "r"(b0));
}

// streaming (evict-first) stores for write-once outputs
__device__ __forceinline__ void stcs_f2(float* p, float a, float b) {
    asm volatile("st.global.cs.v2.f32 [%0], {%1,%2};" :: "l"(p), "f"(a), "f"(b));
}
__device__ __forceinline__ void stcs_f4(float* p, float4 v) {
    asm volatile("st.global.cs.v4.f32 [%0], {%1,%2,%3,%4};"
                 :: "l"(p), "f"(v.x), "f"(v.y), "f"(v.z), "f"(v.w));
}

#define CP_ASYNC16(dst_u32, src_ptr) \
    asm volatile("cp.async.cg.shared.global [%0], [%1], 16;" :: "r"(dst_u32), "l"(src_ptr))
#define CP_COMMIT() asm volatile("cp.async.commit_group;" ::: "memory")
#define CP_WAIT(N)  asm volatile("cp.async.wait_group %0;" :: "n"(N) : "memory")

// ---------------------------------------------------------------------------
// prep: Wvf = Wv @ Wfc  (64x64 @ 64x64)
// ---------------------------------------------------------------------------
__global__ __launch_bounds__(1024) void prep_kernel(const float* __restrict__ Wv,
                                                    const float* __restrict__ Wfc) {
    __shared__ float wv[64*64];
    __shared__ float wf[64*64];
    int tid = threadIdx.x;
    for (int i = tid; i < 4096; i += 1024) { wv[i] = Wv[i]; wf[i] = Wfc[i]; }
    __syncthreads();
    int r = tid >> 4, c4 = (tid & 15) << 2;
    float4 acc = {0.f, 0.f, 0.f, 0.f};
    #pragma unroll 8
    for (int u = 0; u < 64; u++) {
        float a = wv[r*64 + u];
        float4 b = *(const float4*)&wf[u*64 + c4];
        acc.x += a*b.x; acc.y += a*b.y; acc.z += a*b.z; acc.w += a*b.w;
    }
    *(float4*)&g_Wvf[r*64 + c4] = acc;
}

// ---------------------------------------------------------------------------
// projection v2: one W buffer at a time -> smem 49.7 KB -> 4 blocks/SM.
// per (n, h, 64-row l-tile): q = x@(Wq*0.06/32), k = x@Wk, v' = x@Wvf
// outputs fp16; g_v written transposed ([d][l])
// ---------------------------------------------------------------------------
__global__ __launch_bounds__(256, 4) void proj_kernel(const float* __restrict__ x,
                                                      const float* __restrict__ Wq,
                                                      const float* __restrict__ Wk) {
    extern __shared__ float sm[];
    float* xs = sm;               // 64*65
    float* ws = xs + 64*65;       // 64*65 (single W buffer)
    float* os = ws + 64*65;       // 64*64
    const int tid = threadIdx.x;
    const int bid = blockIdx.x;
    const int n = bid >> 8, h = (bid >> 4) & 15, lt = bid & 15;
    const int l0 = lt << 6;
    const float qs = 0.06f / 32.0f;

    for (int idx = tid; idx < 1024; idx += 256) {
        int l = idx >> 4, t4 = (idx & 15) << 2;
        float4 v = *(const float4*)&x[(n*LQ + l0 + l)*EE + (h << 6) + t4];
        float* p = &xs[l*65 + t4];
        p[0] = v.x; p[1] = v.y; p[2] = v.z; p[3] = v.w;
    }

    const int tl = tid & 15, td = tid >> 4;
    for (int w = 0; w < 3; w++) {
        // load this W into the single buffer
        for (int idx = tid; idx < 4096; idx += 256) {
            int t = idx >> 6, d = idx & 63;
            float val;
            if (w == 0)      val = Wq[idx] * qs;
            else if (w == 1) val = Wk[idx];
            else             val = g_Wvf[idx];
            ws[t*65 + d] = val;
        }
        __syncthreads();

        float acc[4][4] = {};
        for (int t = 0; t < 64; t++) {
            float xv[4], wv[4];
            #pragma unroll
            for (int a = 0; a < 4; a++) xv[a] = xs[(tl*4 + a)*65 + t];
            #pragma unroll
            for (int b = 0; b < 4; b++) wv[b] = ws[t*65 + td*4 + b];
            #pragma unroll
            for (int a = 0; a < 4; a++)
                #pragma unroll
                for (int b = 0; b < 4; b++) acc[a][b] += xv[a] * wv[b];
        }
        if (w < 2) {
            #pragma unroll
            for (int a = 0; a < 4; a++)
                #pragma unroll
                for (int b = 0; b < 4; b++)
                    os[(tl*4 + a)*64 + td*4 + b] = acc[a][b];
        } else {
            #pragma unroll
            for (int a = 0; a < 4; a++)
                #pragma unroll
                for (int b = 0; b < 4; b++)
                    os[(td*4 + b)*64 + tl*4 + a] = acc[a][b];
        }
        __syncthreads();
        if (w < 2) {
            __half* gp = (w == 0 ? g_q : g_k) + ((n*HH + h)*LQ + l0)*DD;
            for (int idx = tid; idx < 2048; idx += 256) {
                int row = idx >> 5, d2 = (idx & 31) << 1;
                __half2 hv = __floats2half2_rn(os[row*64 + d2], os[row*64 + d2 + 1]);
                *(__half2*)(gp + row*64 + d2) = hv;
            }
        } else {
            __half* gp = g_v + ((n*HH + h)*DD)*LQ + l0;
            for (int idx = tid; idx < 2048; idx += 256) {
                int d = idx >> 5, l2 = (idx & 31) << 1;
                __half2 hv = __floats2half2_rn(os[d*64 + l2], os[d*64 + l2 + 1]);
                *(__half2*)(gp + d*LQ + l2) = hv;
            }
        }
        __syncthreads();
    }
}

// ---------------------------------------------------------------------------
// attention v7: 16-query block, 256 threads, 8 warps, 2 blocks/SM.
//  3-stage K and V cp.async pipelines (depth-2 prefetch, WAIT(1) discipline),
//  single __syncthreads per phase-3 chunk.
//  phase1: e = exp(s) in FP32 regs; online row-sums (no max: |s|<0.1).
//  normalize: attn from fp32 regs (st.cs); fp16 A-frags packed in-register.
//  phase3: warp partial over its 128 keys; 8-slot smem reduce on overlay.
// smem: KB 3x16K | VB 3x16K | Qs 2K | redS 512B = 100864 B -> 2 blocks/SM
//       reduce overlay [0, 34816) within KB region
// ---------------------------------------------------------------------------
#define SMEM_KB   0
#define SMEM_VB   49152
#define SMEM_QS   98304
#define SMEM_REDS 100352
#define SMEM_TOT  100864

__global__ __launch_bounds__(256, 2) void attn_kernel(float* __restrict__ attn,
                                                      float* __restrict__ out) {
    extern __shared__ char smraw[];
    __half* Qs   = (__half*)(smraw + SMEM_QS);
    float*  redS = (float*)(smraw + SMEM_REDS);
    float*  red  = (float*)(smraw);               // overlay on KB after phase1
    const uint32_t sbase = (uint32_t)__cvta_generic_to_shared(smraw);

    const int tid = threadIdx.x, w = tid >> 5, lane = tid & 31;
    const int bid = blockIdx.x;
    const int n = bid >> 10, h = (bid >> 6) & 15, qb = bid & 63;
    const int q0 = qb << 4;
    const int base = (n*HH + h)*LQ;
    const int g = lane >> 2, tg = lane & 3;

    const __half* kg0 = g_k + (size_t)base * DD;
    const __half* vg0 = g_v + (size_t)(n*HH + h) * DD * LQ;

    // issue K chunks 0 and 1 (two groups)
    #pragma unroll
    for (int t = tid; t < 1024; t += 256) {
        int r = t >> 3, c8 = t & 7;
        CP_ASYNC16(sbase + SMEM_KB + (r*64 + ((c8 ^ (r & 7)) << 3))*2,
                   kg0 + r*64 + c8*8);
    }
    CP_COMMIT();
    #pragma unroll
    for (int t = tid; t < 1024; t += 256) {
        int r = t >> 3, c8 = t & 7;
        CP_ASYNC16(sbase + SMEM_KB + 16384 + (r*64 + ((c8 ^ (r & 7)) << 3))*2,
                   kg0 + 128*DD + r*64 + c8*8);
    }
    CP_COMMIT();

    // load Q tile (16x64 half), swizzled
    if (tid < 128) {
        int r = tid >> 3, c8 = tid & 7;
        const uint4* src = (const uint4*)(g_q + (size_t)(base + q0 + r)*DD) + c8;
        *(uint4*)(Qs + r*64 + ((c8 ^ (r & 7)) << 3)) = *src;
    }
    __syncthreads();

    // Q fragments: 4 k-steps
    uint32_t qf[4][4];
    {
        int r0 = g, r1 = g + 8;
        #pragma unroll
        for (int kk = 0; kk < 4; kk++) {
            int c8a = 2*kk, c8b = 2*kk + 1;
            qf[kk][0] = *(const uint32_t*)(Qs + r0*64 + ((c8a ^ g) << 3) + 2*tg);
            qf[kk][1] = *(const uint32_t*)(Qs + r1*64 + ((c8a ^ g) << 3) + 2*tg);
            qf[kk][2] = *(const uint32_t*)(Qs + r0*64 + ((c8b ^ g) << 3) + 2*tg);
            qf[kk][3] = *(const uint32_t*)(Qs + r1*64 + ((c8b ^ g) << 3) + 2*tg);
        }
    }

    // ---- phase 1: QK^T chunk-streamed (3-stage); e = exp(s) in FP32 regs ----
    float ef[8][2][4];             // [chunk][nt][val]
    float sums[2] = {0.f, 0.f};    // rows g, g+8

    #pragma unroll
    for (int c = 0; c < 8; c++) {
        CP_WAIT(1);                // oldest pending group (K_c) done
        __syncthreads();
        if (c < 6) {               // prefetch K_{c+2} into buffer (c+2)%3
            const __half* kc = kg0 + (size_t)(c + 2)*128*DD;
            #pragma unroll
            for (int t = tid; t < 1024; t += 256) {
                int r = t >> 3, c8 = t & 7;
                CP_ASYNC16(sbase + SMEM_KB + ((c + 2) % 3)*16384
                           + (r*64 + ((c8 ^ (r & 7)) << 3))*2,
                           kc + r*64 + c8*8);
            }
            CP_COMMIT();
        } else if (c == 6) {       // prefetch V0
            #pragma unroll
            for (int t = tid; t < 1024; t += 256) {
                int r = t >> 4, c8 = t & 15;
                CP_ASYNC16(sbase + SMEM_VB + (r*128 + ((c8 ^ (r & 7)) << 3))*2,
                           vg0 + r*LQ + c8*8);
            }
            CP_COMMIT();
        } else {                   // c == 7: prefetch V1
            #pragma unroll
            for (int t = tid; t < 1024; t += 256) {
                int r = t >> 4, c8 = t & 15;
                CP_ASYNC16(sbase + SMEM_VB + 16384
                           + (r*128 + ((c8 ^ (r & 7)) << 3))*2,
                           vg0 + r*LQ + 128 + c8*8);
            }
            CP_COMMIT();
        }
        const __half* Kc = (const __half*)(smraw + SMEM_KB + (c % 3)*16384);
        float a[2][4] = {{0.f,0.f,0.f,0.f},{0.f,0.f,0.f,0.f}};
        #pragma unroll
        for (int kk = 0; kk < 4; kk++) {
            #pragma unroll
            for (int nt = 0; nt < 2; nt++) {
                int krow = w*16 + nt*8 + g;
                uint32_t b0 = *(const uint32_t*)(Kc + krow*64 + (((2*kk)   ^ g) << 3) + 2*tg);
                uint32_t b1 = *(const uint32_t*)(Kc + krow*64 + (((2*kk+1) ^ g) << 3) + 2*tg);
                mma_f16(a[nt], qf[kk][0], qf[kk][1], qf[kk][2], qf[kk][3], b0, b1);
            }
        }
        #pragma unroll
        for (int nt = 0; nt < 2; nt++) {
            float e0 = __expf(a[nt][0]);
            float e1 = __expf(a[nt][1]);
            float e2 = __expf(a[nt][2]);
            float e3 = __expf(a[nt][3]);
            sums[0] += e0 + e1;
            sums[1] += e2 + e3;
            ef[c][nt][0] = e0; ef[c][nt][1] = e1;
            ef[c][nt][2] = e2; ef[c][nt][3] = e3;
        }
    }

    // ---- sum reduce (no max needed: |s| < 0.1) ----
    #pragma unroll
    for (int z = 0; z < 2; z++) {
        float s = sums[z];
        s += __shfl_xor_sync(0xffffffffu, s, 1);
        s += __shfl_xor_sync(0xffffffffu, s, 2);
        sums[z] = s;
    }
    if (tg == 0) {
        redS[(g)*8 + w]     = sums[0];
        redS[(g+8)*8 + w]   = sums[1];
    }
    __syncthreads();
    float inv[2];
    #pragma unroll
    for (int z = 0; z < 2; z++) {
        int row = z*8 + g;
        float s = 0.f;
        #pragma unroll
        for (int k = 0; k < 8; k++) s += redS[row*8 + k];
        inv[z] = 1.0f / s;
    }

    // ---- normalize: attn from fp32 regs (st.cs); pack fp16 A-frags ----
    uint32_t pef[8][2][2];
    #pragma unroll
    for (int c = 0; c < 8; c++)
        #pragma unroll
        for (int nt = 0; nt < 2; nt++) {
            float p0 = ef[c][nt][0] * inv[0];
            float p1 = ef[c][nt][1] * inv[0];
            float p2 = ef[c][nt][2] * inv[1];
            float p3 = ef[c][nt][3] * inv[1];
            int colb = c*128 + w*16 + nt*8 + 2*tg;
            stcs_f2(attn + (size_t)(base + q0 + g)*1024 + colb,     p0, p1);
            stcs_f2(attn + (size_t)(base + q0 + g + 8)*1024 + colb, p2, p3);
            __half2 h0 = __floats2half2_rn(p0, p1);
            __half2 h1 = __floats2half2_rn(p2, p3);
            pef[c][nt][0] = *(uint32_t*)&h0;
            pef[c][nt][1] = *(uint32_t*)&h1;
        }

    // ---- phase 3: out partial over warp's 128 keys (3-stage V pipeline) ----
    float oacc[8][4];
    #pragma unroll
    for (int nt = 0; nt < 8; nt++)
        #pragma unroll
        for (int j = 0; j < 4; j++) oacc[nt][j] = 0.f;

    #pragma unroll
    for (int c = 0; c < 8; c++) {
        if (c < 7) { CP_WAIT(1); } else { CP_WAIT(0); }
        __syncthreads();
        if (c + 2 < 8) {   // prefetch V_{c+2} into buffer (c+2)%3 (not in use)
            const __half* vc = vg0 + (size_t)(c + 2)*128;
            #pragma unroll
            for (int t = tid; t < 1024; t += 256) {
                int r = t >> 4, c8 = t & 15;
                CP_ASYNC16(sbase + SMEM_VB + ((c + 2) % 3)*16384
                           + (r*128 + ((c8 ^ (r & 7)) << 3))*2,
                           vc + r*LQ + c8*8);
            }
            CP_COMMIT();
        }
        const __half* Vc = (const __half*)(smraw + SMEM_VB + (c % 3)*16384);
        #pragma unroll
        for (int kk = 0; kk < 2; kk++) {
            #pragma unroll
            for (int nt = 0; nt < 8; nt++) {
                int vrow = nt*8 + g;   // dim index (vrow & 7 == g)
                uint32_t b = *(const uint32_t*)(Vc + vrow*128
                              + (((w*2 + kk) ^ g) << 3) + 2*tg);
                mma_f16_k8(oacc[nt], pef[c][kk][0], pef[c][kk][1], b);
            }
        }
    }

    // ---- single-pass 8-slot reduce (overlay on KB smem, unused in phase3) ----
    {
        int slot = w;
        #pragma unroll
        for (int nt = 0; nt < 8; nt++) {
            int d0 = nt*8 + 2*tg;
            *(float2*)&red[slot*1088 + g*68 + d0]
                = make_float2(oacc[nt][0], oacc[nt][1]);
            *(float2*)&red[slot*1088 + (g+8)*68 + d0]
                = make_float2(oacc[nt][2], oacc[nt][3]);
        }
    }
    __syncthreads();
    {
        int row = tid >> 4, d4 = (tid & 15) << 2;
        float4 s = make_float4(0.f, 0.f, 0.f, 0.f);
        #pragma unroll
        for (int k = 0; k < 8; k++) {
            float4 v = *(const float4*)&red[k*1088 + row*68 + d4];
            s.x += v.x; s.y += v.y; s.z += v.z; s.w += v.w;
        }
        stcs_f4(&out[((size_t)(n*LQ + q0 + row)*HH + h)*DD + d4], s);
    }
}

// ---------------------------------------------------------------------------
extern "C" void kernel_launch(void* const* d_in, const int* in_sizes, int n_in,
                              void* d_out, int out_size) {
    const float* x   = (const float*)d_in[0];
    const float* Wq  = (const float*)d_in[1];
    const float* Wk  = (const float*)d_in[2];
    const float* Wv  = (const float*)d_in[3];
    const float* Wfc = (const float*)d_in[4];

    float* out  = (float*)d_out;
    float* attn = out + (size_t)NB * LQ * EE;   // out first, then attn

    prep_kernel<<<1, 1024>>>(Wv, Wfc);

    size_t proj_smem = (size_t)(2*64*65 + 64*64) * sizeof(float);   // 49664
    cudaFuncSetAttribute(proj_kernel,
                         cudaFuncAttributeMaxDynamicSharedMemorySize,
                         (int)proj_smem);
    proj_kernel<<<NB*HH*16, 256, proj_smem>>>(x, Wq, Wk);

    cudaFuncSetAttribute(attn_kernel,
                         cudaFuncAttributeMaxDynamicSharedMemorySize,
                         SMEM_TOT);
    attn_kernel<<<NB*HH*64, 256, SMEM_TOT>>>(attn, out);
}